// round 13
// baseline (speedup 1.0000x reference)
#include <cuda_runtime.h>
#include <cuda_fp16.h>
#include <math.h>
#include <stdint.h>

#define BATCH    2
#define SEQL     4096
#define DMODEL   2048
#define DINNER   4096
#define NHEADS   64
#define HEADDIM  64
#define DSTATE   16
#define CONVDIM  4128
#define INDIM    8288
#define NROWS    (BATCH*SEQL)
#define DTCOL    (DINNER + CONVDIM)

#define NPAD1    8448          // 33 * 256
#define NPAD2    2048          // 8 * 256

#define NCHUNK   64
#define CHL      64
#define NBH      (BATCH*NHEADS)   // 128

// ---------------- scratch ----------------
__device__ float g_zx [(size_t)NROWS * INDIM];
__device__ float g_xbc[(size_t)NROWS * CONVDIM];
__device__ float g_dtv[NROWS * NHEADS];
__device__ float g_dAv[NROWS * NHEADS];
__device__ float g_y  [(size_t)NROWS * DINNER];

__device__ float g_S    [(size_t)NCHUNK * NBH * HEADDIM * DSTATE];
__device__ float g_P    [NCHUNK * NBH];
__device__ float g_Hinit[(size_t)NCHUNK * NBH * HEADDIM * DSTATE];

// A-hat: [M, 2K] = [hi | lo] along K.  B-hat: [Npad, K] hi only.
__device__ __align__(256) __half g_ah1[(size_t)NROWS * 2 * DMODEL];
__device__ __align__(256) __half g_bh1[(size_t)NPAD1 * DMODEL];
__device__ __align__(256) __half g_ah2[(size_t)NROWS * 2 * DINNER];
__device__ __align__(256) __half g_bh2[(size_t)NPAD2 * DINNER];

// ---------------- PTX helpers ----------------
__device__ __forceinline__ uint32_t smem_u32(const void* p) {
    uint32_t a;
    asm("{ .reg .u64 t; cvta.to.shared.u64 t, %1; cvt.u32.u64 %0, t; }" : "=r"(a) : "l"(p));
    return a;
}
__device__ __forceinline__ void cp16(uint32_t dst, const void* src) {
    asm volatile("cp.async.cg.shared.global [%0], [%1], 16;" :: "r"(dst), "l"(src));
}
__device__ __forceinline__ void cp_commit() { asm volatile("cp.async.commit_group;"); }
template <int N> __device__ __forceinline__ void cp_wait() {
    asm volatile("cp.async.wait_group %0;" :: "n"(N));
}
__device__ __forceinline__ void ldsm4(uint32_t* r, uint32_t addr) {
    asm volatile("ldmatrix.sync.aligned.m8n8.x4.shared.b16 {%0,%1,%2,%3}, [%4];"
        : "=r"(r[0]), "=r"(r[1]), "=r"(r[2]), "=r"(r[3]) : "r"(addr));
}
__device__ __forceinline__ void mma16816(float* c, const uint32_t* a, const uint32_t* b) {
    asm volatile("mma.sync.aligned.m16n8k16.row.col.f32.f16.f16.f32 "
        "{%0,%1,%2,%3}, {%4,%5,%6,%7}, {%8,%9}, {%0,%1,%2,%3};"
        : "+f"(c[0]), "+f"(c[1]), "+f"(c[2]), "+f"(c[3])
        : "r"(a[0]), "r"(a[1]), "r"(a[2]), "r"(a[3]), "r"(b[0]), "r"(b[1]));
}
#define SW128(off) ((off) ^ (((off) >> 3) & 0x70))

// ================= fp16 HMMA GEMM: 128x256 tile, shared-B two-term k-loop =================
#define AHI_ST  16384
#define B_OFF   32768
#define STAGE_B 65536
#define N_STG   3
#define GEMM_SMEM (N_STG*STAGE_B)   // 192 KB

__global__ __launch_bounds__(256, 1)
void gemm_mma(const __half* __restrict__ A, const __half* __restrict__ B,
              float* __restrict__ C, int K, int Nreal, int ldC)
{
    extern __shared__ __align__(1024) char smem[];
    const uint32_t sb0 = smem_u32(smem);
    const int tid  = threadIdx.x;
    const int wid  = tid >> 5, lane = tid & 31;
    const int wm   = wid & 1, wn = wid >> 1;
    const int bm   = blockIdx.y << 7;
    const int bn   = blockIdx.x << 8;
    const int KT   = K >> 6;

    const char* Ab = (const char*)A + (size_t)bm * 2 * K * 2;
    const char* Bb = (const char*)B + (size_t)bn * K * 2;
    const size_t rstrideA = (size_t)2 * K * 2;
    const size_t rstrideB = (size_t)K * 2;

    const int ldrow = tid >> 3;
    const int ldcol = (tid & 7) << 4;

    auto load_tile = [&](int kt, int st) {
        uint32_t shi = sb0 + st * STAGE_B;
        uint32_t slo = shi + AHI_ST;
        uint32_t sbp = shi + B_OFF;
        const char* ahsrc = Ab + (size_t)kt * 128;
        const char* alsrc = Ab + (size_t)K * 2 + (size_t)kt * 128;
        const char* bsrc  = Bb + (size_t)kt * 128;
        #pragma unroll
        for (int i = 0; i < 4; i++) {
            int row = ldrow + i * 32;
            cp16(shi + SW128(row * 128 + ldcol), ahsrc + (size_t)row * rstrideA + ldcol);
            cp16(slo + SW128(row * 128 + ldcol), alsrc + (size_t)row * rstrideA + ldcol);
        }
        #pragma unroll
        for (int i = 0; i < 8; i++) {
            int row = ldrow + i * 32;
            cp16(sbp + SW128(row * 128 + ldcol), bsrc + (size_t)row * rstrideB + ldcol);
        }
    };

    float acc[4][8][4];
    #pragma unroll
    for (int i = 0; i < 4; i++)
        #pragma unroll
        for (int j = 0; j < 8; j++)
            #pragma unroll
            for (int q = 0; q < 4; q++) acc[i][j][q] = 0.f;

    const int aRow  = wm * 64 + (lane & 15);
    const int aKoff = (lane >> 4) << 4;
    const int bRow  = wn * 64 + ((lane >> 4) << 3) + (lane & 7);
    const int bKoff = ((lane >> 3) & 1) << 4;

    load_tile(0, 0); cp_commit();
    load_tile(1, 1); cp_commit();

    for (int kt = 0; kt < KT; kt++) {
        cp_wait<1>();
        __syncthreads();
        int st = kt % N_STG;
        if (kt + 2 < KT) load_tile(kt + 2, (kt + 2) % N_STG);
        cp_commit();

        uint32_t shi = sb0 + st * STAGE_B;
        uint32_t slo = shi + AHI_ST;
        uint32_t sbp = shi + B_OFF;

        #pragma unroll
        for (int j = 0; j < 4; j++) {
            uint32_t ahf[4][4], alf[4][4], bf[4][4];
            #pragma unroll
            for (int im = 0; im < 4; im++) {
                int row = aRow + im * 16;
                uint32_t off = row * 128 + ((j * 32 + aKoff) ^ ((row & 7) << 4));
                ldsm4(ahf[im], shi + off);
                ldsm4(alf[im], slo + off);
            }
            #pragma unroll
            for (int in2 = 0; in2 < 4; in2++) {
                int row = bRow + in2 * 16;
                ldsm4(bf[in2], sbp + row * 128 + ((j * 32 + bKoff) ^ ((row & 7) << 4)));
            }
            #pragma unroll
            for (int im = 0; im < 4; im++)
                #pragma unroll
                for (int inn = 0; inn < 8; inn++) {
                    mma16816(acc[im][inn], ahf[im], &bf[inn >> 1][(inn & 1) * 2]);
                    mma16816(acc[im][inn], alf[im], &bf[inn >> 1][(inn & 1) * 2]);
                }
        }
    }

    const int crow0 = bm + wm * 64 + (lane >> 2);
    const int ccol0 = bn + wn * 64 + (lane & 3) * 2;
    #pragma unroll
    for (int im = 0; im < 4; im++) {
        #pragma unroll
        for (int inn = 0; inn < 8; inn++) {
            int col = ccol0 + inn * 8;
            if (col + 1 < Nreal) {
                int r0 = crow0 + im * 16;
                *(float2*)&C[(size_t)r0 * ldC + col]       = make_float2(acc[im][inn][0], acc[im][inn][1]);
                *(float2*)&C[(size_t)(r0 + 8) * ldC + col] = make_float2(acc[im][inn][2], acc[im][inn][3]);
            } else if (col < Nreal) {
                int r0 = crow0 + im * 16;
                C[(size_t)r0 * ldC + col]       = acc[im][inn][0];
                C[(size_t)(r0 + 8) * ldC + col] = acc[im][inn][2];
            }
        }
    }
}

// ================= split kernels =================
__device__ __forceinline__ void split2h(float x, __half& hi, __half& lo) {
    hi = __float2half_rn(x);
    lo = __float2half_rn(x - __half2float(hi));
}

__global__ void split_a_kernel(const float* __restrict__ in, __half* __restrict__ out, int K)
{
    int idx = blockIdx.x * 256 + threadIdx.x;
    int m = idx / K, k = idx - m * K;
    float x = in[idx];
    __half hi, lo; split2h(x, hi, lo);
    size_t ro = (size_t)m * 2 * K;
    out[ro + k] = hi; out[ro + K + k] = lo;
}

__global__ void split_b_kernel(const float* __restrict__ in, __half* __restrict__ out,
                               int K, int N, int Npad)
{
    __shared__ float t[32][33];
    int n0 = blockIdx.x * 32, k0 = blockIdx.y * 32;
    int tx = threadIdx.x, ty = threadIdx.y;
    #pragma unroll
    for (int i = 0; i < 4; i++) {
        int k = k0 + ty + i * 8, n = n0 + tx;
        t[ty + i * 8][tx] = (n < N) ? in[(size_t)k * N + n] : 0.f;
    }
    __syncthreads();
    #pragma unroll
    for (int i = 0; i < 4; i++) {
        int n = n0 + ty + i * 8, k = k0 + tx;
        if (n < Npad)
            out[(size_t)n * K + k] = __float2half_rn(t[tx][ty + i * 8]);
    }
}

// ================= conv + silu =================
__global__ void conv_silu_kernel(const float* __restrict__ cw, const float* __restrict__ cb)
{
    int c = blockIdx.x * 128 + threadIdx.x;
    if (c >= CONVDIM) return;
    int b = blockIdx.z, l0 = blockIdx.y * 64;
    float w0 = cw[c*4+0], w1 = cw[c*4+1], w2 = cw[c*4+2], w3 = cw[c*4+3];
    float bias = cb[c];
    const float* src = g_zx  + (size_t)b * SEQL * INDIM + DINNER + c;
    float*       dst = g_xbc + (size_t)b * SEQL * CONVDIM + c;
    float x0 = (l0 - 3 >= 0) ? src[(size_t)(l0-3) * INDIM] : 0.f;
    float x1 = (l0 - 2 >= 0) ? src[(size_t)(l0-2) * INDIM] : 0.f;
    float x2 = (l0 - 1 >= 0) ? src[(size_t)(l0-1) * INDIM] : 0.f;
    for (int l = l0; l < l0 + 64; l++) {
        float x3 = src[(size_t)l * INDIM];
        float v  = bias + w0*x0 + w1*x1 + w2*x2 + w3*x3;
        dst[(size_t)l * CONVDIM] = v / (1.f + __expf(-v));
        x0 = x1; x1 = x2; x2 = x3;
    }
}

// ================= dt: softplus + dA =================
__global__ void dt_kernel(const float* __restrict__ A_log, const float* __restrict__ dt_bias)
{
    int idx = blockIdx.x * blockDim.x + threadIdx.x;
    if (idx >= NROWS * NHEADS) return;
    int row = idx >> 6, h = idx & 63;
    float raw = g_zx[(size_t)row * INDIM + DTCOL + h] + dt_bias[h];
    float dt  = (raw > 20.f) ? raw : log1pf(expf(raw));
    g_dtv[idx] = dt;
    g_dAv[idx] = expf(dt * -expf(A_log[h]));
}

// ================= chunked scan: phase A =================
__global__ void scanA_kernel()
{
    int bh = blockIdx.x;
    int c  = blockIdx.y;
    int b = bh >> 6, h = bh & 63, p = threadIdx.x;

    float st[DSTATE];
    #pragma unroll
    for (int n = 0; n < DSTATE; n++) st[n] = 0.f;
    float pprod = 1.f;

    const size_t xbase = (size_t)b * SEQL * CONVDIM;
    for (int i = 0; i < CHL; i++) {
        int l = c * CHL + i;
        const float* r = g_xbc + xbase + (size_t)l * CONVDIM;
        int rowi = b * SEQL + l;
        float x = r[h * HEADDIM + p];
        const float4* Bp = (const float4*)(r + DINNER);
        float4 b0 = Bp[0], b1 = Bp[1], b2 = Bp[2], b3 = Bp[3];
        float bb[16] = { b0.x,b0.y,b0.z,b0.w, b1.x,b1.y,b1.z,b1.w,
                         b2.x,b2.y,b2.z,b2.w, b3.x,b3.y,b3.z,b3.w };
        float dt = g_dtv[rowi * NHEADS + h];
        float dA = g_dAv[rowi * NHEADS + h];
        float dtx = dt * x;
        #pragma unroll
        for (int n = 0; n < DSTATE; n++) st[n] = st[n] * dA + dtx * bb[n];
        pprod *= dA;
    }
    float* Sout = g_S + ((size_t)c * NBH + bh) * (HEADDIM * DSTATE) + p * DSTATE;
    #pragma unroll
    for (int n = 0; n < DSTATE; n++) Sout[n] = st[n];
    if (p == 0) g_P[c * NBH + bh] = pprod;
}

// ================= phase B =================
__global__ void scanB_kernel()
{
    int bh = blockIdx.x;
    int p  = threadIdx.x;
    float h[DSTATE];
    #pragma unroll
    for (int n = 0; n < DSTATE; n++) h[n] = 0.f;

    for (int c = 0; c < NCHUNK; c++) {
        size_t base = ((size_t)c * NBH + bh) * (HEADDIM * DSTATE) + p * DSTATE;
        float* Hout = g_Hinit + base;
        #pragma unroll
        for (int n = 0; n < DSTATE; n++) Hout[n] = h[n];
        float P = g_P[c * NBH + bh];
        const float* Sin = g_S + base;
        #pragma unroll
        for (int n = 0; n < DSTATE; n++) h[n] = h[n] * P + Sin[n];
    }
}

// ================= phase C =================
__global__ void scanC_kernel(const float* __restrict__ D_skip)
{
    int bh = blockIdx.x;
    int c  = blockIdx.y;
    int b = bh >> 6, h = bh & 63, p = threadIdx.x;

    float st[DSTATE];
    const float* Hin = g_Hinit + ((size_t)c * NBH + bh) * (HEADDIM * DSTATE) + p * DSTATE;
    #pragma unroll
    for (int n = 0; n < DSTATE; n++) st[n] = Hin[n];

    const float Dh = D_skip[h];
    const size_t xbase = (size_t)b * SEQL * CONVDIM;
    for (int i = 0; i < CHL; i++) {
        int l = c * CHL + i;
        const float* r = g_xbc + xbase + (size_t)l * CONVDIM;
        int rowi = b * SEQL + l;
        float x = r[h * HEADDIM + p];
        const float4* Bp = (const float4*)(r + DINNER);
        const float4* Cp = (const float4*)(r + DINNER + DSTATE);
        float4 b0 = Bp[0], b1 = Bp[1], b2 = Bp[2], b3 = Bp[3];
        float4 c0 = Cp[0], c1 = Cp[1], c2 = Cp[2], c3 = Cp[3];
        float bb[16] = { b0.x,b0.y,b0.z,b0.w, b1.x,b1.y,b1.z,b1.w,
                         b2.x,b2.y,b2.z,b2.w, b3.x,b3.y,b3.z,b3.w };
        float cc[16] = { c0.x,c0.y,c0.z,c0.w, c1.x,c1.y,c1.z,c1.w,
                         c2.x,c2.y,c2.z,c2.w, c3.x,c3.y,c3.z,c3.w };
        float dt = g_dtv[rowi * NHEADS + h];
        float dA = g_dAv[rowi * NHEADS + h];
        float dtx = dt * x;
        float y0 = 0.f, y1 = 0.f, y2 = 0.f, y3 = 0.f;
        #pragma unroll
        for (int n = 0; n < DSTATE; n += 4) {
            st[n+0] = st[n+0] * dA + dtx * bb[n+0]; y0 += st[n+0] * cc[n+0];
            st[n+1] = st[n+1] * dA + dtx * bb[n+1]; y1 += st[n+1] * cc[n+1];
            st[n+2] = st[n+2] * dA + dtx * bb[n+2]; y2 += st[n+2] * cc[n+2];
            st[n+3] = st[n+3] * dA + dtx * bb[n+3]; y3 += st[n+3] * cc[n+3];
        }
        float y = (y0 + y1) + (y2 + y3);
        float g = g_zx[(size_t)rowi * INDIM + h * HEADDIM + p];
        float sg = g / (1.f + __expf(-g));
        g_y[(size_t)rowi * DINNER + h * HEADDIM + p] = (y + Dh * x) * sg;
    }
}

// ================= RMSNorm fused with A-hat split for GEMM2 =================
__global__ void rmsnorm_split_kernel(const float* __restrict__ norm_w, __half* __restrict__ out)
{
    int row = blockIdx.x, tid = threadIdx.x;
    const float* r = g_y + (size_t)row * DINNER;
    float ss = 0.f;
    for (int c = tid; c < DINNER; c += 256) { float v = r[c]; ss += v * v; }
    __shared__ float red[256];
    red[tid] = ss;
    __syncthreads();
    #pragma unroll
    for (int s = 128; s > 0; s >>= 1) { if (tid < s) red[tid] += red[tid + s]; __syncthreads(); }
    float rstd = rsqrtf(red[0] / (float)DINNER + 1e-5f);
    size_t ro = (size_t)row * 2 * DINNER;
    for (int c = tid; c < DINNER; c += 256) {
        float v = r[c] * rstd * norm_w[c];
        __half hi, lo; split2h(v, hi, lo);
        out[ro + c] = hi; out[ro + DINNER + c] = lo;
    }
}

// ================= launch =================
extern "C" void kernel_launch(void* const* d_in, const int* in_sizes, int n_in,
                              void* d_out, int out_size)
{
    const float* hs      = (const float*)d_in[0];
    const float* W_in    = (const float*)d_in[1];
    const float* conv_w  = (const float*)d_in[2];
    const float* conv_b  = (const float*)d_in[3];
    const float* A_log   = (const float*)d_in[4];
    const float* D_skip  = (const float*)d_in[5];
    const float* dt_bias = (const float*)d_in[6];
    const float* norm_w  = (const float*)d_in[7];
    const float* W_out   = (const float*)d_in[8];
    float* out = (float*)d_out;

    float *zx = nullptr;
    __half *ah1, *bh1, *ah2, *bh2;
    cudaGetSymbolAddress((void**)&zx,  g_zx);
    cudaGetSymbolAddress((void**)&ah1, g_ah1);
    cudaGetSymbolAddress((void**)&bh1, g_bh1);
    cudaGetSymbolAddress((void**)&ah2, g_ah2);
    cudaGetSymbolAddress((void**)&bh2, g_bh2);

    cudaFuncSetAttribute(gemm_mma, cudaFuncAttributeMaxDynamicSharedMemorySize, GEMM_SMEM);

    // one-time side stream + events (host resources only; identical GPU work per call;
    // created on the harness's pre-capture correctness call, so never inside capture)
    static cudaStream_t s2 = nullptr;
    static cudaEvent_t evFork = nullptr, evJoin = nullptr;
    if (s2 == nullptr) {
        cudaStreamCreateWithFlags(&s2, cudaStreamNonBlocking);
        cudaEventCreateWithFlags(&evFork, cudaEventDisableTiming);
        cudaEventCreateWithFlags(&evJoin, cudaEventDisableTiming);
    }

    split_a_kernel<<<(NROWS * DMODEL) / 256, 256>>>(hs, ah1, DMODEL);
    split_b_kernel<<<dim3(NPAD1 / 32, DMODEL / 32), dim3(32, 8)>>>(W_in, bh1, DMODEL, INDIM, NPAD1);
    split_b_kernel<<<dim3(NPAD2 / 32, DINNER / 32), dim3(32, 8)>>>(W_out, bh2, DINNER, DMODEL, NPAD2);

    // 1a) zx cols [4096, 8288): xBC + dt portion (B rows 4096.., C offset +4096)
    gemm_mma<<<dim3(17, NROWS / 128), 256, GEMM_SMEM>>>(
        ah1, bh1 + (size_t)DINNER * DMODEL, zx + DINNER, DMODEL, INDIM - DINNER, INDIM);

    // fork: side stream consumes xBC+dt while main stream computes the gate columns
    cudaEventRecord(evFork, 0);
    cudaStreamWaitEvent(s2, evFork, 0);

    conv_silu_kernel<<<dim3((CONVDIM + 127) / 128, SEQL / 64, BATCH), 128, 0, s2>>>(conv_w, conv_b);
    dt_kernel<<<(NROWS * NHEADS) / 256, 256, 0, s2>>>(A_log, dt_bias);
    scanA_kernel<<<dim3(NBH, NCHUNK), HEADDIM, 0, s2>>>();
    scanB_kernel<<<NBH, HEADDIM, 0, s2>>>();
    cudaEventRecord(evJoin, s2);

    // 1b) zx cols [0, 4096): gate portion — overlaps with the side stream above
    gemm_mma<<<dim3(16, NROWS / 128), 256, GEMM_SMEM>>>(ah1, bh1, zx, DMODEL, DINNER, INDIM);

    // join: scanC needs both the gate (main) and Hinit (side)
    cudaStreamWaitEvent(0, evJoin, 0);

    scanC_kernel<<<dim3(NBH, NCHUNK), HEADDIM>>>(D_skip);
    rmsnorm_split_kernel<<<NROWS, 256>>>(norm_w, ah2);

    // 2) out = y @ W_out
    gemm_mma<<<dim3(NPAD2 / 256, NROWS / 128), 256, GEMM_SMEM>>>(ah2, bh2, out, DINNER, DMODEL, DMODEL);
}

// round 14
// speedup vs baseline: 1.1285x; 1.1285x over previous
#include <cuda_runtime.h>
#include <cuda_fp16.h>
#include <math.h>
#include <stdint.h>

#define BATCH    2
#define SEQL     4096
#define DMODEL   2048
#define DINNER   4096
#define NHEADS   64
#define HEADDIM  64
#define DSTATE   16
#define CONVDIM  4128
#define INDIM    8288
#define NROWS    (BATCH*SEQL)
#define DTCOL    (DINNER + CONVDIM)

#define NPAD1    8448          // 33 * 256
#define NPAD2    2048          // 8 * 256

#define NCHUNK   64
#define CHL      64
#define NBH      (BATCH*NHEADS)   // 128

// ---------------- scratch ----------------
__device__ float g_zx [(size_t)NROWS * INDIM];
__device__ float g_xbc[(size_t)NROWS * CONVDIM];
__device__ float g_dtv[NROWS * NHEADS];
__device__ float g_dAv[NROWS * NHEADS];
__device__ float g_y  [(size_t)NROWS * DINNER];

__device__ float g_S    [(size_t)NCHUNK * NBH * HEADDIM * DSTATE];
__device__ float g_P    [NCHUNK * NBH];
__device__ float g_Hinit[(size_t)NCHUNK * NBH * HEADDIM * DSTATE];

// GEMM1 A-hat: [M, 2K] = [hi | lo].  GEMM2 A-hat: [M, K] hi-only.  B-hats: [Npad, K] hi.
__device__ __align__(256) __half g_ah1[(size_t)NROWS * 2 * DMODEL];
__device__ __align__(256) __half g_bh1[(size_t)NPAD1 * DMODEL];
__device__ __align__(256) __half g_ah2[(size_t)NROWS * DINNER];
__device__ __align__(256) __half g_bh2[(size_t)NPAD2 * DINNER];

// ---------------- PTX helpers ----------------
__device__ __forceinline__ uint32_t smem_u32(const void* p) {
    uint32_t a;
    asm("{ .reg .u64 t; cvta.to.shared.u64 t, %1; cvt.u32.u64 %0, t; }" : "=r"(a) : "l"(p));
    return a;
}
__device__ __forceinline__ void cp16(uint32_t dst, const void* src) {
    asm volatile("cp.async.cg.shared.global [%0], [%1], 16;" :: "r"(dst), "l"(src));
}
__device__ __forceinline__ void cp_commit() { asm volatile("cp.async.commit_group;"); }
template <int N> __device__ __forceinline__ void cp_wait() {
    asm volatile("cp.async.wait_group %0;" :: "n"(N));
}
__device__ __forceinline__ void ldsm4(uint32_t* r, uint32_t addr) {
    asm volatile("ldmatrix.sync.aligned.m8n8.x4.shared.b16 {%0,%1,%2,%3}, [%4];"
        : "=r"(r[0]), "=r"(r[1]), "=r"(r[2]), "=r"(r[3]) : "r"(addr));
}
__device__ __forceinline__ void mma16816(float* c, const uint32_t* a, const uint32_t* b) {
    asm volatile("mma.sync.aligned.m16n8k16.row.col.f32.f16.f16.f32 "
        "{%0,%1,%2,%3}, {%4,%5,%6,%7}, {%8,%9}, {%0,%1,%2,%3};"
        : "+f"(c[0]), "+f"(c[1]), "+f"(c[2]), "+f"(c[3])
        : "r"(a[0]), "r"(a[1]), "r"(a[2]), "r"(a[3]), "r"(b[0]), "r"(b[1]));
}
#define SW128(off) ((off) ^ (((off) >> 3) & 0x70))

// ================= fp16 HMMA GEMM: 128x256 tile, TERMS-term shared-B k-loop =================
// TERMS=2: A-hat rows are [hi | lo] (stride 2K); both terms hit one B tile.
// TERMS=1: plain fp16 GEMM (stride K).
#define AHI_ST  16384
#define B_OFF   32768
#define STAGE_B 65536
#define N_STG   3
#define GEMM_SMEM (N_STG*STAGE_B)   // 192 KB

template <int TERMS>
__global__ __launch_bounds__(256, 1)
void gemm_mma(const __half* __restrict__ A, const __half* __restrict__ B,
              float* __restrict__ C, int K, int Nreal, int ldC)
{
    extern __shared__ __align__(1024) char smem[];
    const uint32_t sb0 = smem_u32(smem);
    const int tid  = threadIdx.x;
    const int wid  = tid >> 5, lane = tid & 31;
    const int wm   = wid & 1, wn = wid >> 1;
    const int bm   = blockIdx.y << 7;
    const int bn   = blockIdx.x << 8;
    const int KT   = K >> 6;

    const char* Ab = (const char*)A + (size_t)bm * TERMS * K * 2;
    const char* Bb = (const char*)B + (size_t)bn * K * 2;
    const size_t rstrideA = (size_t)TERMS * K * 2;
    const size_t rstrideB = (size_t)K * 2;

    const int ldrow = tid >> 3;
    const int ldcol = (tid & 7) << 4;

    auto load_tile = [&](int kt, int st) {
        uint32_t shi = sb0 + st * STAGE_B;
        uint32_t slo = shi + AHI_ST;
        uint32_t sbp = shi + B_OFF;
        const char* ahsrc = Ab + (size_t)kt * 128;
        const char* alsrc = Ab + (size_t)K * 2 + (size_t)kt * 128;
        const char* bsrc  = Bb + (size_t)kt * 128;
        #pragma unroll
        for (int i = 0; i < 4; i++) {
            int row = ldrow + i * 32;
            cp16(shi + SW128(row * 128 + ldcol), ahsrc + (size_t)row * rstrideA + ldcol);
            if (TERMS == 2)
                cp16(slo + SW128(row * 128 + ldcol), alsrc + (size_t)row * rstrideA + ldcol);
        }
        #pragma unroll
        for (int i = 0; i < 8; i++) {
            int row = ldrow + i * 32;
            cp16(sbp + SW128(row * 128 + ldcol), bsrc + (size_t)row * rstrideB + ldcol);
        }
    };

    float acc[4][8][4];
    #pragma unroll
    for (int i = 0; i < 4; i++)
        #pragma unroll
        for (int j = 0; j < 8; j++)
            #pragma unroll
            for (int q = 0; q < 4; q++) acc[i][j][q] = 0.f;

    const int aRow  = wm * 64 + (lane & 15);
    const int aKoff = (lane >> 4) << 4;
    const int bRow  = wn * 64 + ((lane >> 4) << 3) + (lane & 7);
    const int bKoff = ((lane >> 3) & 1) << 4;

    load_tile(0, 0); cp_commit();
    load_tile(1, 1); cp_commit();

    for (int kt = 0; kt < KT; kt++) {
        cp_wait<1>();
        __syncthreads();
        int st = kt % N_STG;
        if (kt + 2 < KT) load_tile(kt + 2, (kt + 2) % N_STG);
        cp_commit();

        uint32_t shi = sb0 + st * STAGE_B;
        uint32_t slo = shi + AHI_ST;
        uint32_t sbp = shi + B_OFF;

        #pragma unroll
        for (int j = 0; j < 4; j++) {
            uint32_t ahf[4][4], alf[4][4], bf[4][4];
            #pragma unroll
            for (int im = 0; im < 4; im++) {
                int row = aRow + im * 16;
                uint32_t off = row * 128 + ((j * 32 + aKoff) ^ ((row & 7) << 4));
                ldsm4(ahf[im], shi + off);
                if (TERMS == 2) ldsm4(alf[im], slo + off);
            }
            #pragma unroll
            for (int in2 = 0; in2 < 4; in2++) {
                int row = bRow + in2 * 16;
                ldsm4(bf[in2], sbp + row * 128 + ((j * 32 + bKoff) ^ ((row & 7) << 4)));
            }
            #pragma unroll
            for (int im = 0; im < 4; im++)
                #pragma unroll
                for (int inn = 0; inn < 8; inn++) {
                    mma16816(acc[im][inn], ahf[im], &bf[inn >> 1][(inn & 1) * 2]);
                    if (TERMS == 2)
                        mma16816(acc[im][inn], alf[im], &bf[inn >> 1][(inn & 1) * 2]);
                }
        }
    }

    const int crow0 = bm + wm * 64 + (lane >> 2);
    const int ccol0 = bn + wn * 64 + (lane & 3) * 2;
    #pragma unroll
    for (int im = 0; im < 4; im++) {
        #pragma unroll
        for (int inn = 0; inn < 8; inn++) {
            int col = ccol0 + inn * 8;
            if (col + 1 < Nreal) {
                int r0 = crow0 + im * 16;
                *(float2*)&C[(size_t)r0 * ldC + col]       = make_float2(acc[im][inn][0], acc[im][inn][1]);
                *(float2*)&C[(size_t)(r0 + 8) * ldC + col] = make_float2(acc[im][inn][2], acc[im][inn][3]);
            } else if (col < Nreal) {
                int r0 = crow0 + im * 16;
                C[(size_t)r0 * ldC + col]       = acc[im][inn][0];
                C[(size_t)(r0 + 8) * ldC + col] = acc[im][inn][2];
            }
        }
    }
}

// ================= split kernels =================
__device__ __forceinline__ void split2h(float x, __half& hi, __half& lo) {
    hi = __float2half_rn(x);
    lo = __float2half_rn(x - __half2float(hi));
}

__global__ void split_a_kernel(const float* __restrict__ in, __half* __restrict__ out, int K)
{
    int idx = blockIdx.x * 256 + threadIdx.x;
    int m = idx / K, k = idx - m * K;
    float x = in[idx];
    __half hi, lo; split2h(x, hi, lo);
    size_t ro = (size_t)m * 2 * K;
    out[ro + k] = hi; out[ro + K + k] = lo;
}

__global__ void split_b_kernel(const float* __restrict__ in, __half* __restrict__ out,
                               int K, int N, int Npad)
{
    __shared__ float t[32][33];
    int n0 = blockIdx.x * 32, k0 = blockIdx.y * 32;
    int tx = threadIdx.x, ty = threadIdx.y;
    #pragma unroll
    for (int i = 0; i < 4; i++) {
        int k = k0 + ty + i * 8, n = n0 + tx;
        t[ty + i * 8][tx] = (n < N) ? in[(size_t)k * N + n] : 0.f;
    }
    __syncthreads();
    #pragma unroll
    for (int i = 0; i < 4; i++) {
        int n = n0 + ty + i * 8, k = k0 + tx;
        if (n < Npad)
            out[(size_t)n * K + k] = __float2half_rn(t[tx][ty + i * 8]);
    }
}

// ================= conv + silu =================
__global__ void conv_silu_kernel(const float* __restrict__ cw, const float* __restrict__ cb)
{
    int c = blockIdx.x * 128 + threadIdx.x;
    if (c >= CONVDIM) return;
    int b = blockIdx.z, l0 = blockIdx.y * 64;
    float w0 = cw[c*4+0], w1 = cw[c*4+1], w2 = cw[c*4+2], w3 = cw[c*4+3];
    float bias = cb[c];
    const float* src = g_zx  + (size_t)b * SEQL * INDIM + DINNER + c;
    float*       dst = g_xbc + (size_t)b * SEQL * CONVDIM + c;
    float x0 = (l0 - 3 >= 0) ? src[(size_t)(l0-3) * INDIM] : 0.f;
    float x1 = (l0 - 2 >= 0) ? src[(size_t)(l0-2) * INDIM] : 0.f;
    float x2 = (l0 - 1 >= 0) ? src[(size_t)(l0-1) * INDIM] : 0.f;
    for (int l = l0; l < l0 + 64; l++) {
        float x3 = src[(size_t)l * INDIM];
        float v  = bias + w0*x0 + w1*x1 + w2*x2 + w3*x3;
        dst[(size_t)l * CONVDIM] = v / (1.f + __expf(-v));
        x0 = x1; x1 = x2; x2 = x3;
    }
}

// ================= dt: softplus + dA =================
__global__ void dt_kernel(const float* __restrict__ A_log, const float* __restrict__ dt_bias)
{
    int idx = blockIdx.x * blockDim.x + threadIdx.x;
    if (idx >= NROWS * NHEADS) return;
    int row = idx >> 6, h = idx & 63;
    float raw = g_zx[(size_t)row * INDIM + DTCOL + h] + dt_bias[h];
    float dt  = (raw > 20.f) ? raw : log1pf(expf(raw));
    g_dtv[idx] = dt;
    g_dAv[idx] = expf(dt * -expf(A_log[h]));
}

// ================= chunked scan: phase A =================
__global__ void scanA_kernel()
{
    int bh = blockIdx.x;
    int c  = blockIdx.y;
    int b = bh >> 6, h = bh & 63, p = threadIdx.x;

    float st[DSTATE];
    #pragma unroll
    for (int n = 0; n < DSTATE; n++) st[n] = 0.f;
    float pprod = 1.f;

    const size_t xbase = (size_t)b * SEQL * CONVDIM;
    for (int i = 0; i < CHL; i++) {
        int l = c * CHL + i;
        const float* r = g_xbc + xbase + (size_t)l * CONVDIM;
        int rowi = b * SEQL + l;
        float x = r[h * HEADDIM + p];
        const float4* Bp = (const float4*)(r + DINNER);
        float4 b0 = Bp[0], b1 = Bp[1], b2 = Bp[2], b3 = Bp[3];
        float bb[16] = { b0.x,b0.y,b0.z,b0.w, b1.x,b1.y,b1.z,b1.w,
                         b2.x,b2.y,b2.z,b2.w, b3.x,b3.y,b3.z,b3.w };
        float dt = g_dtv[rowi * NHEADS + h];
        float dA = g_dAv[rowi * NHEADS + h];
        float dtx = dt * x;
        #pragma unroll
        for (int n = 0; n < DSTATE; n++) st[n] = st[n] * dA + dtx * bb[n];
        pprod *= dA;
    }
    float* Sout = g_S + ((size_t)c * NBH + bh) * (HEADDIM * DSTATE) + p * DSTATE;
    #pragma unroll
    for (int n = 0; n < DSTATE; n++) Sout[n] = st[n];
    if (p == 0) g_P[c * NBH + bh] = pprod;
}

// ================= phase B =================
__global__ void scanB_kernel()
{
    int bh = blockIdx.x;
    int p  = threadIdx.x;
    float h[DSTATE];
    #pragma unroll
    for (int n = 0; n < DSTATE; n++) h[n] = 0.f;

    for (int c = 0; c < NCHUNK; c++) {
        size_t base = ((size_t)c * NBH + bh) * (HEADDIM * DSTATE) + p * DSTATE;
        float* Hout = g_Hinit + base;
        #pragma unroll
        for (int n = 0; n < DSTATE; n++) Hout[n] = h[n];
        float P = g_P[c * NBH + bh];
        const float* Sin = g_S + base;
        #pragma unroll
        for (int n = 0; n < DSTATE; n++) h[n] = h[n] * P + Sin[n];
    }
}

// ================= phase C =================
__global__ void scanC_kernel(const float* __restrict__ D_skip)
{
    int bh = blockIdx.x;
    int c  = blockIdx.y;
    int b = bh >> 6, h = bh & 63, p = threadIdx.x;

    float st[DSTATE];
    const float* Hin = g_Hinit + ((size_t)c * NBH + bh) * (HEADDIM * DSTATE) + p * DSTATE;
    #pragma unroll
    for (int n = 0; n < DSTATE; n++) st[n] = Hin[n];

    const float Dh = D_skip[h];
    const size_t xbase = (size_t)b * SEQL * CONVDIM;
    for (int i = 0; i < CHL; i++) {
        int l = c * CHL + i;
        const float* r = g_xbc + xbase + (size_t)l * CONVDIM;
        int rowi = b * SEQL + l;
        float x = r[h * HEADDIM + p];
        const float4* Bp = (const float4*)(r + DINNER);
        const float4* Cp = (const float4*)(r + DINNER + DSTATE);
        float4 b0 = Bp[0], b1 = Bp[1], b2 = Bp[2], b3 = Bp[3];
        float4 c0 = Cp[0], c1 = Cp[1], c2 = Cp[2], c3 = Cp[3];
        float bb[16] = { b0.x,b0.y,b0.z,b0.w, b1.x,b1.y,b1.z,b1.w,
                         b2.x,b2.y,b2.z,b2.w, b3.x,b3.y,b3.z,b3.w };
        float cc[16] = { c0.x,c0.y,c0.z,c0.w, c1.x,c1.y,c1.z,c1.w,
                         c2.x,c2.y,c2.z,c2.w, c3.x,c3.y,c3.z,c3.w };
        float dt = g_dtv[rowi * NHEADS + h];
        float dA = g_dAv[rowi * NHEADS + h];
        float dtx = dt * x;
        float y0 = 0.f, y1 = 0.f, y2 = 0.f, y3 = 0.f;
        #pragma unroll
        for (int n = 0; n < DSTATE; n += 4) {
            st[n+0] = st[n+0] * dA + dtx * bb[n+0]; y0 += st[n+0] * cc[n+0];
            st[n+1] = st[n+1] * dA + dtx * bb[n+1]; y1 += st[n+1] * cc[n+1];
            st[n+2] = st[n+2] * dA + dtx * bb[n+2]; y2 += st[n+2] * cc[n+2];
            st[n+3] = st[n+3] * dA + dtx * bb[n+3]; y3 += st[n+3] * cc[n+3];
        }
        float y = (y0 + y1) + (y2 + y3);
        float g = g_zx[(size_t)rowi * INDIM + h * HEADDIM + p];
        float sg = g / (1.f + __expf(-g));
        g_y[(size_t)rowi * DINNER + h * HEADDIM + p] = (y + Dh * x) * sg;
    }
}

// ================= RMSNorm fused with hi-only A-hat for GEMM2 =================
__global__ void rmsnorm_split_kernel(const float* __restrict__ norm_w, __half* __restrict__ out)
{
    int row = blockIdx.x, tid = threadIdx.x;
    const float* r = g_y + (size_t)row * DINNER;
    float ss = 0.f;
    for (int c = tid; c < DINNER; c += 256) { float v = r[c]; ss += v * v; }
    __shared__ float red[256];
    red[tid] = ss;
    __syncthreads();
    #pragma unroll
    for (int s = 128; s > 0; s >>= 1) { if (tid < s) red[tid] += red[tid + s]; __syncthreads(); }
    float rstd = rsqrtf(red[0] / (float)DINNER + 1e-5f);
    size_t ro = (size_t)row * DINNER;
    for (int c = tid; c < DINNER; c += 256)
        out[ro + c] = __float2half_rn(r[c] * rstd * norm_w[c]);
}

// ================= launch =================
extern "C" void kernel_launch(void* const* d_in, const int* in_sizes, int n_in,
                              void* d_out, int out_size)
{
    const float* hs      = (const float*)d_in[0];
    const float* W_in    = (const float*)d_in[1];
    const float* conv_w  = (const float*)d_in[2];
    const float* conv_b  = (const float*)d_in[3];
    const float* A_log   = (const float*)d_in[4];
    const float* D_skip  = (const float*)d_in[5];
    const float* dt_bias = (const float*)d_in[6];
    const float* norm_w  = (const float*)d_in[7];
    const float* W_out   = (const float*)d_in[8];
    float* out = (float*)d_out;

    float *zx = nullptr;
    __half *ah1, *bh1, *ah2, *bh2;
    cudaGetSymbolAddress((void**)&zx,  g_zx);
    cudaGetSymbolAddress((void**)&ah1, g_ah1);
    cudaGetSymbolAddress((void**)&bh1, g_bh1);
    cudaGetSymbolAddress((void**)&ah2, g_ah2);
    cudaGetSymbolAddress((void**)&bh2, g_bh2);

    cudaFuncSetAttribute(gemm_mma<2>, cudaFuncAttributeMaxDynamicSharedMemorySize, GEMM_SMEM);
    cudaFuncSetAttribute(gemm_mma<1>, cudaFuncAttributeMaxDynamicSharedMemorySize, GEMM_SMEM);

    split_a_kernel<<<(NROWS * DMODEL) / 256, 256>>>(hs, ah1, DMODEL);
    split_b_kernel<<<dim3(NPAD1 / 32, DMODEL / 32), dim3(32, 8)>>>(W_in, bh1, DMODEL, INDIM, NPAD1);
    split_b_kernel<<<dim3(NPAD2 / 32, DINNER / 32), dim3(32, 8)>>>(W_out, bh2, DINNER, DMODEL, NPAD2);

    // 1) zxbcdt = hs @ W_in   (2-term, single launch)
    gemm_mma<2><<<dim3(NPAD1 / 256, NROWS / 128), 256, GEMM_SMEM>>>(ah1, bh1, zx, DMODEL, INDIM, INDIM);

    // 2) conv + dt
    conv_silu_kernel<<<dim3((CONVDIM + 127) / 128, SEQL / 64, BATCH), 128>>>(conv_w, conv_b);
    dt_kernel<<<(NROWS * NHEADS) / 256, 256>>>(A_log, dt_bias);

    // 3) chunked parallel scan
    scanA_kernel<<<dim3(NBH, NCHUNK), HEADDIM>>>();
    scanB_kernel<<<NBH, HEADDIM>>>();
    scanC_kernel<<<dim3(NBH, NCHUNK), HEADDIM>>>(D_skip);

    // 4) rmsnorm + hi-only fp16 cast
    rmsnorm_split_kernel<<<NROWS, 256>>>(norm_w, ah2);

    // 5) out = y @ W_out   (single-term fp16)
    gemm_mma<1><<<dim3(NPAD2 / 256, NROWS / 128), 256, GEMM_SMEM>>>(ah2, bh2, out, DINNER, DMODEL, DMODEL);
}

// round 15
// speedup vs baseline: 1.2530x; 1.1103x over previous
#include <cuda_runtime.h>
#include <cuda_fp16.h>
#include <math.h>
#include <stdint.h>

#define BATCH    2
#define SEQL     4096
#define DMODEL   2048
#define DINNER   4096
#define NHEADS   64
#define HEADDIM  64
#define DSTATE   16
#define CONVDIM  4128
#define INDIM    8288
#define NROWS    (BATCH*SEQL)
#define DTCOL    (DINNER + CONVDIM)

#define NPAD1    8448          // 33 * 256
#define NPAD2    2048          // 8 * 256

#define NCHUNK   64
#define CHL      64
#define NBH      (BATCH*NHEADS)   // 128

// ---------------- scratch ----------------
__device__ float g_zx [(size_t)NROWS * INDIM];
__device__ float g_xbc[(size_t)NROWS * CONVDIM];
__device__ float g_dtv[NROWS * NHEADS];
__device__ float g_dAv[NROWS * NHEADS];
__device__ float g_y  [(size_t)NROWS * DINNER];

__device__ float g_S    [(size_t)NCHUNK * NBH * HEADDIM * DSTATE];
__device__ float g_P    [NCHUNK * NBH];
__device__ float g_Hinit[(size_t)NCHUNK * NBH * HEADDIM * DSTATE];

// GEMM1 A-hat: [M, 2K] = [hi | lo].  GEMM2 A-hat: [M, K] hi-only.  B-hats: [Npad, K] hi.
__device__ __align__(256) __half g_ah1[(size_t)NROWS * 2 * DMODEL];
__device__ __align__(256) __half g_bh1[(size_t)NPAD1 * DMODEL];
__device__ __align__(256) __half g_ah2[(size_t)NROWS * DINNER];
__device__ __align__(256) __half g_bh2[(size_t)NPAD2 * DINNER];

// ---------------- PTX helpers ----------------
__device__ __forceinline__ uint32_t smem_u32(const void* p) {
    uint32_t a;
    asm("{ .reg .u64 t; cvta.to.shared.u64 t, %1; cvt.u32.u64 %0, t; }" : "=r"(a) : "l"(p));
    return a;
}
__device__ __forceinline__ void cp16(uint32_t dst, const void* src) {
    asm volatile("cp.async.cg.shared.global [%0], [%1], 16;" :: "r"(dst), "l"(src));
}
__device__ __forceinline__ void cp_commit() { asm volatile("cp.async.commit_group;"); }
template <int N> __device__ __forceinline__ void cp_wait() {
    asm volatile("cp.async.wait_group %0;" :: "n"(N));
}
__device__ __forceinline__ void ldsm4(uint32_t* r, uint32_t addr) {
    asm volatile("ldmatrix.sync.aligned.m8n8.x4.shared.b16 {%0,%1,%2,%3}, [%4];"
        : "=r"(r[0]), "=r"(r[1]), "=r"(r[2]), "=r"(r[3]) : "r"(addr));
}
__device__ __forceinline__ void mma16816(float* c, const uint32_t* a, const uint32_t* b) {
    asm volatile("mma.sync.aligned.m16n8k16.row.col.f32.f16.f16.f32 "
        "{%0,%1,%2,%3}, {%4,%5,%6,%7}, {%8,%9}, {%0,%1,%2,%3};"
        : "+f"(c[0]), "+f"(c[1]), "+f"(c[2]), "+f"(c[3])
        : "r"(a[0]), "r"(a[1]), "r"(a[2]), "r"(a[3]), "r"(b[0]), "r"(b[1]));
}
#define SW128(off) ((off) ^ (((off) >> 3) & 0x70))

// ================= fp16 HMMA GEMM: 128x256 tile, TERMS-term shared-B k-loop =================
// TERMS=2 (requires ASTR=2): A rows are [hi | lo]; both terms hit one B tile.
// TERMS=1: hi-only GEMM; ASTR = A row stride in units of K (2 when A keeps a lo block).
#define AHI_ST  16384
#define B_OFF   32768
#define STAGE_B 65536
#define N_STG   3
#define GEMM_SMEM (N_STG*STAGE_B)   // 192 KB

template <int TERMS, int ASTR>
__global__ __launch_bounds__(256, 1)
void gemm_mma(const __half* __restrict__ A, const __half* __restrict__ B,
              float* __restrict__ C, int K, int Nreal, int ldC)
{
    extern __shared__ __align__(1024) char smem[];
    const uint32_t sb0 = smem_u32(smem);
    const int tid  = threadIdx.x;
    const int wid  = tid >> 5, lane = tid & 31;
    const int wm   = wid & 1, wn = wid >> 1;
    const int bm   = blockIdx.y << 7;
    const int bn   = blockIdx.x << 8;
    const int KT   = K >> 6;

    const char* Ab = (const char*)A + (size_t)bm * ASTR * K * 2;
    const char* Bb = (const char*)B + (size_t)bn * K * 2;
    const size_t rstrideA = (size_t)ASTR * K * 2;
    const size_t rstrideB = (size_t)K * 2;

    const int ldrow = tid >> 3;
    const int ldcol = (tid & 7) << 4;

    auto load_tile = [&](int kt, int st) {
        uint32_t shi = sb0 + st * STAGE_B;
        uint32_t slo = shi + AHI_ST;
        uint32_t sbp = shi + B_OFF;
        const char* ahsrc = Ab + (size_t)kt * 128;
        const char* alsrc = Ab + (size_t)K * 2 + (size_t)kt * 128;
        const char* bsrc  = Bb + (size_t)kt * 128;
        #pragma unroll
        for (int i = 0; i < 4; i++) {
            int row = ldrow + i * 32;
            cp16(shi + SW128(row * 128 + ldcol), ahsrc + (size_t)row * rstrideA + ldcol);
            if (TERMS == 2)
                cp16(slo + SW128(row * 128 + ldcol), alsrc + (size_t)row * rstrideA + ldcol);
        }
        #pragma unroll
        for (int i = 0; i < 8; i++) {
            int row = ldrow + i * 32;
            cp16(sbp + SW128(row * 128 + ldcol), bsrc + (size_t)row * rstrideB + ldcol);
        }
    };

    float acc[4][8][4];
    #pragma unroll
    for (int i = 0; i < 4; i++)
        #pragma unroll
        for (int j = 0; j < 8; j++)
            #pragma unroll
            for (int q = 0; q < 4; q++) acc[i][j][q] = 0.f;

    const int aRow  = wm * 64 + (lane & 15);
    const int aKoff = (lane >> 4) << 4;
    const int bRow  = wn * 64 + ((lane >> 4) << 3) + (lane & 7);
    const int bKoff = ((lane >> 3) & 1) << 4;

    load_tile(0, 0); cp_commit();
    load_tile(1, 1); cp_commit();

    for (int kt = 0; kt < KT; kt++) {
        cp_wait<1>();
        __syncthreads();
        int st = kt % N_STG;
        if (kt + 2 < KT) load_tile(kt + 2, (kt + 2) % N_STG);
        cp_commit();

        uint32_t shi = sb0 + st * STAGE_B;
        uint32_t slo = shi + AHI_ST;
        uint32_t sbp = shi + B_OFF;

        #pragma unroll
        for (int j = 0; j < 4; j++) {
            uint32_t ahf[4][4], alf[4][4], bf[4][4];
            #pragma unroll
            for (int im = 0; im < 4; im++) {
                int row = aRow + im * 16;
                uint32_t off = row * 128 + ((j * 32 + aKoff) ^ ((row & 7) << 4));
                ldsm4(ahf[im], shi + off);
                if (TERMS == 2) ldsm4(alf[im], slo + off);
            }
            #pragma unroll
            for (int in2 = 0; in2 < 4; in2++) {
                int row = bRow + in2 * 16;
                ldsm4(bf[in2], sbp + row * 128 + ((j * 32 + bKoff) ^ ((row & 7) << 4)));
            }
            #pragma unroll
            for (int im = 0; im < 4; im++)
                #pragma unroll
                for (int inn = 0; inn < 8; inn++) {
                    mma16816(acc[im][inn], ahf[im], &bf[inn >> 1][(inn & 1) * 2]);
                    if (TERMS == 2)
                        mma16816(acc[im][inn], alf[im], &bf[inn >> 1][(inn & 1) * 2]);
                }
        }
    }

    const int crow0 = bm + wm * 64 + (lane >> 2);
    const int ccol0 = bn + wn * 64 + (lane & 3) * 2;
    #pragma unroll
    for (int im = 0; im < 4; im++) {
        #pragma unroll
        for (int inn = 0; inn < 8; inn++) {
            int col = ccol0 + inn * 8;
            if (col + 1 < Nreal) {
                int r0 = crow0 + im * 16;
                *(float2*)&C[(size_t)r0 * ldC + col]       = make_float2(acc[im][inn][0], acc[im][inn][1]);
                *(float2*)&C[(size_t)(r0 + 8) * ldC + col] = make_float2(acc[im][inn][2], acc[im][inn][3]);
            } else if (col < Nreal) {
                int r0 = crow0 + im * 16;
                C[(size_t)r0 * ldC + col]       = acc[im][inn][0];
                C[(size_t)(r0 + 8) * ldC + col] = acc[im][inn][2];
            }
        }
    }
}

// ================= split kernels =================
__device__ __forceinline__ void split2h(float x, __half& hi, __half& lo) {
    hi = __float2half_rn(x);
    lo = __float2half_rn(x - __half2float(hi));
}

__global__ void split_a_kernel(const float* __restrict__ in, __half* __restrict__ out, int K)
{
    int idx = blockIdx.x * 256 + threadIdx.x;
    int m = idx / K, k = idx - m * K;
    float x = in[idx];
    __half hi, lo; split2h(x, hi, lo);
    size_t ro = (size_t)m * 2 * K;
    out[ro + k] = hi; out[ro + K + k] = lo;
}

__global__ void split_b_kernel(const float* __restrict__ in, __half* __restrict__ out,
                               int K, int N, int Npad)
{
    __shared__ float t[32][33];
    int n0 = blockIdx.x * 32, k0 = blockIdx.y * 32;
    int tx = threadIdx.x, ty = threadIdx.y;
    #pragma unroll
    for (int i = 0; i < 4; i++) {
        int k = k0 + ty + i * 8, n = n0 + tx;
        t[ty + i * 8][tx] = (n < N) ? in[(size_t)k * N + n] : 0.f;
    }
    __syncthreads();
    #pragma unroll
    for (int i = 0; i < 4; i++) {
        int n = n0 + ty + i * 8, k = k0 + tx;
        if (n < Npad)
            out[(size_t)n * K + k] = __float2half_rn(t[tx][ty + i * 8]);
    }
}

// ================= conv + silu =================
__global__ void conv_silu_kernel(const float* __restrict__ cw, const float* __restrict__ cb)
{
    int c = blockIdx.x * 128 + threadIdx.x;
    if (c >= CONVDIM) return;
    int b = blockIdx.z, l0 = blockIdx.y * 64;
    float w0 = cw[c*4+0], w1 = cw[c*4+1], w2 = cw[c*4+2], w3 = cw[c*4+3];
    float bias = cb[c];
    const float* src = g_zx  + (size_t)b * SEQL * INDIM + DINNER + c;
    float*       dst = g_xbc + (size_t)b * SEQL * CONVDIM + c;
    float x0 = (l0 - 3 >= 0) ? src[(size_t)(l0-3) * INDIM] : 0.f;
    float x1 = (l0 - 2 >= 0) ? src[(size_t)(l0-2) * INDIM] : 0.f;
    float x2 = (l0 - 1 >= 0) ? src[(size_t)(l0-1) * INDIM] : 0.f;
    for (int l = l0; l < l0 + 64; l++) {
        float x3 = src[(size_t)l * INDIM];
        float v  = bias + w0*x0 + w1*x1 + w2*x2 + w3*x3;
        dst[(size_t)l * CONVDIM] = v / (1.f + __expf(-v));
        x0 = x1; x1 = x2; x2 = x3;
    }
}

// ================= dt: softplus + dA =================
__global__ void dt_kernel(const float* __restrict__ A_log, const float* __restrict__ dt_bias)
{
    int idx = blockIdx.x * blockDim.x + threadIdx.x;
    if (idx >= NROWS * NHEADS) return;
    int row = idx >> 6, h = idx & 63;
    float raw = g_zx[(size_t)row * INDIM + DTCOL + h] + dt_bias[h];
    float dt  = (raw > 20.f) ? raw : log1pf(expf(raw));
    g_dtv[idx] = dt;
    g_dAv[idx] = expf(dt * -expf(A_log[h]));
}

// ================= chunked scan: phase A =================
__global__ void scanA_kernel()
{
    int bh = blockIdx.x;
    int c  = blockIdx.y;
    int b = bh >> 6, h = bh & 63, p = threadIdx.x;

    float st[DSTATE];
    #pragma unroll
    for (int n = 0; n < DSTATE; n++) st[n] = 0.f;
    float pprod = 1.f;

    const size_t xbase = (size_t)b * SEQL * CONVDIM;
    for (int i = 0; i < CHL; i++) {
        int l = c * CHL + i;
        const float* r = g_xbc + xbase + (size_t)l * CONVDIM;
        int rowi = b * SEQL + l;
        float x = r[h * HEADDIM + p];
        const float4* Bp = (const float4*)(r + DINNER);
        float4 b0 = Bp[0], b1 = Bp[1], b2 = Bp[2], b3 = Bp[3];
        float bb[16] = { b0.x,b0.y,b0.z,b0.w, b1.x,b1.y,b1.z,b1.w,
                         b2.x,b2.y,b2.z,b2.w, b3.x,b3.y,b3.z,b3.w };
        float dt = g_dtv[rowi * NHEADS + h];
        float dA = g_dAv[rowi * NHEADS + h];
        float dtx = dt * x;
        #pragma unroll
        for (int n = 0; n < DSTATE; n++) st[n] = st[n] * dA + dtx * bb[n];
        pprod *= dA;
    }
    float* Sout = g_S + ((size_t)c * NBH + bh) * (HEADDIM * DSTATE) + p * DSTATE;
    #pragma unroll
    for (int n = 0; n < DSTATE; n++) Sout[n] = st[n];
    if (p == 0) g_P[c * NBH + bh] = pprod;
}

// ================= phase B =================
__global__ void scanB_kernel()
{
    int bh = blockIdx.x;
    int p  = threadIdx.x;
    float h[DSTATE];
    #pragma unroll
    for (int n = 0; n < DSTATE; n++) h[n] = 0.f;

    for (int c = 0; c < NCHUNK; c++) {
        size_t base = ((size_t)c * NBH + bh) * (HEADDIM * DSTATE) + p * DSTATE;
        float* Hout = g_Hinit + base;
        #pragma unroll
        for (int n = 0; n < DSTATE; n++) Hout[n] = h[n];
        float P = g_P[c * NBH + bh];
        const float* Sin = g_S + base;
        #pragma unroll
        for (int n = 0; n < DSTATE; n++) h[n] = h[n] * P + Sin[n];
    }
}

// ================= phase C =================
__global__ void scanC_kernel(const float* __restrict__ D_skip)
{
    int bh = blockIdx.x;
    int c  = blockIdx.y;
    int b = bh >> 6, h = bh & 63, p = threadIdx.x;

    float st[DSTATE];
    const float* Hin = g_Hinit + ((size_t)c * NBH + bh) * (HEADDIM * DSTATE) + p * DSTATE;
    #pragma unroll
    for (int n = 0; n < DSTATE; n++) st[n] = Hin[n];

    const float Dh = D_skip[h];
    const size_t xbase = (size_t)b * SEQL * CONVDIM;
    for (int i = 0; i < CHL; i++) {
        int l = c * CHL + i;
        const float* r = g_xbc + xbase + (size_t)l * CONVDIM;
        int rowi = b * SEQL + l;
        float x = r[h * HEADDIM + p];
        const float4* Bp = (const float4*)(r + DINNER);
        const float4* Cp = (const float4*)(r + DINNER + DSTATE);
        float4 b0 = Bp[0], b1 = Bp[1], b2 = Bp[2], b3 = Bp[3];
        float4 c0 = Cp[0], c1 = Cp[1], c2 = Cp[2], c3 = Cp[3];
        float bb[16] = { b0.x,b0.y,b0.z,b0.w, b1.x,b1.y,b1.z,b1.w,
                         b2.x,b2.y,b2.z,b2.w, b3.x,b3.y,b3.z,b3.w };
        float cc[16] = { c0.x,c0.y,c0.z,c0.w, c1.x,c1.y,c1.z,c1.w,
                         c2.x,c2.y,c2.z,c2.w, c3.x,c3.y,c3.z,c3.w };
        float dt = g_dtv[rowi * NHEADS + h];
        float dA = g_dAv[rowi * NHEADS + h];
        float dtx = dt * x;
        float y0 = 0.f, y1 = 0.f, y2 = 0.f, y3 = 0.f;
        #pragma unroll
        for (int n = 0; n < DSTATE; n += 4) {
            st[n+0] = st[n+0] * dA + dtx * bb[n+0]; y0 += st[n+0] * cc[n+0];
            st[n+1] = st[n+1] * dA + dtx * bb[n+1]; y1 += st[n+1] * cc[n+1];
            st[n+2] = st[n+2] * dA + dtx * bb[n+2]; y2 += st[n+2] * cc[n+2];
            st[n+3] = st[n+3] * dA + dtx * bb[n+3]; y3 += st[n+3] * cc[n+3];
        }
        float y = (y0 + y1) + (y2 + y3);
        float g = g_zx[(size_t)rowi * INDIM + h * HEADDIM + p];
        float sg = g / (1.f + __expf(-g));
        g_y[(size_t)rowi * DINNER + h * HEADDIM + p] = (y + Dh * x) * sg;
    }
}

// ================= RMSNorm fused with hi-only A-hat for GEMM2 =================
__global__ void rmsnorm_split_kernel(const float* __restrict__ norm_w, __half* __restrict__ out)
{
    int row = blockIdx.x, tid = threadIdx.x;
    const float* r = g_y + (size_t)row * DINNER;
    float ss = 0.f;
    for (int c = tid; c < DINNER; c += 256) { float v = r[c]; ss += v * v; }
    __shared__ float red[256];
    red[tid] = ss;
    __syncthreads();
    #pragma unroll
    for (int s = 128; s > 0; s >>= 1) { if (tid < s) red[tid] += red[tid + s]; __syncthreads(); }
    float rstd = rsqrtf(red[0] / (float)DINNER + 1e-5f);
    size_t ro = (size_t)row * DINNER;
    for (int c = tid; c < DINNER; c += 256)
        out[ro + c] = __float2half_rn(r[c] * rstd * norm_w[c]);
}

// ================= launch =================
extern "C" void kernel_launch(void* const* d_in, const int* in_sizes, int n_in,
                              void* d_out, int out_size)
{
    const float* hs      = (const float*)d_in[0];
    const float* W_in    = (const float*)d_in[1];
    const float* conv_w  = (const float*)d_in[2];
    const float* conv_b  = (const float*)d_in[3];
    const float* A_log   = (const float*)d_in[4];
    const float* D_skip  = (const float*)d_in[5];
    const float* dt_bias = (const float*)d_in[6];
    const float* norm_w  = (const float*)d_in[7];
    const float* W_out   = (const float*)d_in[8];
    float* out = (float*)d_out;

    float *zx = nullptr;
    __half *ah1, *bh1, *ah2, *bh2;
    cudaGetSymbolAddress((void**)&zx,  g_zx);
    cudaGetSymbolAddress((void**)&ah1, g_ah1);
    cudaGetSymbolAddress((void**)&bh1, g_bh1);
    cudaGetSymbolAddress((void**)&ah2, g_ah2);
    cudaGetSymbolAddress((void**)&bh2, g_bh2);

    cudaFuncSetAttribute(gemm_mma<2,2>, cudaFuncAttributeMaxDynamicSharedMemorySize, GEMM_SMEM);
    cudaFuncSetAttribute(gemm_mma<1,2>, cudaFuncAttributeMaxDynamicSharedMemorySize, GEMM_SMEM);
    cudaFuncSetAttribute(gemm_mma<1,1>, cudaFuncAttributeMaxDynamicSharedMemorySize, GEMM_SMEM);

    split_a_kernel<<<(NROWS * DMODEL) / 256, 256>>>(hs, ah1, DMODEL);
    split_b_kernel<<<dim3(NPAD1 / 32, DMODEL / 32), dim3(32, 8)>>>(W_in, bh1, DMODEL, INDIM, NPAD1);
    split_b_kernel<<<dim3(NPAD2 / 32, DINNER / 32), dim3(32, 8)>>>(W_out, bh2, DINNER, DMODEL, NPAD2);

    // 1a) gate columns [0, 4096): hi-only (linear path through silu — fp16 rounding OK)
    gemm_mma<1,2><<<dim3(16, NROWS / 128), 256, GEMM_SMEM>>>(ah1, bh1, zx, DMODEL, INDIM, INDIM);

    // 1b) xBC + dt columns [4096, 8448): 2-term (scan-sensitive: B, C, dt)
    gemm_mma<2,2><<<dim3(17, NROWS / 128), 256, GEMM_SMEM>>>(
        ah1, bh1 + (size_t)DINNER * DMODEL, zx + DINNER, DMODEL, INDIM - DINNER, INDIM);

    // 2) conv + dt
    conv_silu_kernel<<<dim3((CONVDIM + 127) / 128, SEQL / 64, BATCH), 128>>>(conv_w, conv_b);
    dt_kernel<<<(NROWS * NHEADS) / 256, 256>>>(A_log, dt_bias);

    // 3) chunked parallel scan
    scanA_kernel<<<dim3(NBH, NCHUNK), HEADDIM>>>();
    scanB_kernel<<<NBH, HEADDIM>>>();
    scanC_kernel<<<dim3(NBH, NCHUNK), HEADDIM>>>(D_skip);

    // 4) rmsnorm + hi-only fp16 cast
    rmsnorm_split_kernel<<<NROWS, 256>>>(norm_w, ah2);

    // 5) out = y @ W_out   (single-term fp16)
    gemm_mma<1,1><<<dim3(NPAD2 / 256, NROWS / 128), 256, GEMM_SMEM>>>(ah2, bh2, out, DINNER, DMODEL, DMODEL);
}

// round 17
// speedup vs baseline: 1.4363x; 1.1463x over previous
#include <cuda_runtime.h>
#include <cuda_fp16.h>
#include <math.h>
#include <stdint.h>

#define BATCH    2
#define SEQL     4096
#define DMODEL   2048
#define DINNER   4096
#define NHEADS   64
#define HEADDIM  64
#define DSTATE   16
#define CONVDIM  4128
#define INDIM    8288
#define NROWS    (BATCH*SEQL)
#define DTCOL    (DINNER + CONVDIM)

#define NPAD1    8448          // 33 * 256
#define NPAD2    2048          // 8 * 256
#define N1TERM   8192          // cols [0, 8192): 1-term (gate + x);  [8192, 8448): 2-term (B, C, dt)

#define NCHUNK   64
#define CHL      64
#define NBH      (BATCH*NHEADS)   // 128

// ---------------- scratch ----------------
__device__ float g_zx [(size_t)NROWS * INDIM];
__device__ float g_xbc[(size_t)NROWS * CONVDIM];
__device__ float g_dtv[NROWS * NHEADS];
__device__ float g_dAv[NROWS * NHEADS];
__device__ float g_y  [(size_t)NROWS * DINNER];

__device__ float g_S    [(size_t)NCHUNK * NBH * HEADDIM * DSTATE];
__device__ float g_P    [NCHUNK * NBH];
__device__ float g_Hinit[(size_t)NCHUNK * NBH * HEADDIM * DSTATE];

// GEMM1 A-hat: [M, 2K] = [hi | lo].  GEMM2 A-hat: [M, K] hi-only.  B-hats: [Npad, K] hi.
__device__ __align__(256) __half g_ah1[(size_t)NROWS * 2 * DMODEL];
__device__ __align__(256) __half g_bh1[(size_t)NPAD1 * DMODEL];
__device__ __align__(256) __half g_ah2[(size_t)NROWS * DINNER];
__device__ __align__(256) __half g_bh2[(size_t)NPAD2 * DINNER];

// ---------------- PTX helpers ----------------
__device__ __forceinline__ uint32_t smem_u32(const void* p) {
    uint32_t a;
    asm("{ .reg .u64 t; cvta.to.shared.u64 t, %1; cvt.u32.u64 %0, t; }" : "=r"(a) : "l"(p));
    return a;
}
__device__ __forceinline__ void cp16(uint32_t dst, const void* src) {
    asm volatile("cp.async.cg.shared.global [%0], [%1], 16;" :: "r"(dst), "l"(src));
}
__device__ __forceinline__ void cp_commit() { asm volatile("cp.async.commit_group;"); }
template <int N> __device__ __forceinline__ void cp_wait() {
    asm volatile("cp.async.wait_group %0;" :: "n"(N));
}
__device__ __forceinline__ void ldsm4(uint32_t* r, uint32_t addr) {
    asm volatile("ldmatrix.sync.aligned.m8n8.x4.shared.b16 {%0,%1,%2,%3}, [%4];"
        : "=r"(r[0]), "=r"(r[1]), "=r"(r[2]), "=r"(r[3]) : "r"(addr));
}
__device__ __forceinline__ void mma16816(float* c, const uint32_t* a, const uint32_t* b) {
    asm volatile("mma.sync.aligned.m16n8k16.row.col.f32.f16.f16.f32 "
        "{%0,%1,%2,%3}, {%4,%5,%6,%7}, {%8,%9}, {%0,%1,%2,%3};"
        : "+f"(c[0]), "+f"(c[1]), "+f"(c[2]), "+f"(c[3])
        : "r"(a[0]), "r"(a[1]), "r"(a[2]), "r"(a[3]), "r"(b[0]), "r"(b[1]));
}
#define SW128(off) ((off) ^ (((off) >> 3) & 0x70))

// ================= fp16 HMMA GEMM: 128x256 tile, TERMS-term shared-B k-loop =================
// TERMS=2 (requires ASTR=2): A rows are [hi | lo]; both terms hit one B tile.
// TERMS=1: hi-only GEMM; ASTR = A row stride in units of K (2 when A keeps a lo block).
#define AHI_ST  16384
#define B_OFF   32768
#define STAGE_B 65536
#define N_STG   3
#define GEMM_SMEM (N_STG*STAGE_B)   // 192 KB

template <int TERMS, int ASTR>
__global__ __launch_bounds__(256, 1)
void gemm_mma(const __half* __restrict__ A, const __half* __restrict__ B,
              float* __restrict__ C, int K, int Nreal, int ldC)
{
    extern __shared__ __align__(1024) char smem[];
    const uint32_t sb0 = smem_u32(smem);
    const int tid  = threadIdx.x;
    const int wid  = tid >> 5, lane = tid & 31;
    const int wm   = wid & 1, wn = wid >> 1;
    const int bm   = blockIdx.y << 7;
    const int bn   = blockIdx.x << 8;
    const int KT   = K >> 6;

    const char* Ab = (const char*)A + (size_t)bm * ASTR * K * 2;
    const char* Bb = (const char*)B + (size_t)bn * K * 2;
    const size_t rstrideA = (size_t)ASTR * K * 2;
    const size_t rstrideB = (size_t)K * 2;

    const int ldrow = tid >> 3;
    const int ldcol = (tid & 7) << 4;

    auto load_tile = [&](int kt, int st) {
        uint32_t shi = sb0 + st * STAGE_B;
        uint32_t slo = shi + AHI_ST;
        uint32_t sbp = shi + B_OFF;
        const char* ahsrc = Ab + (size_t)kt * 128;
        const char* alsrc = Ab + (size_t)K * 2 + (size_t)kt * 128;
        const char* bsrc  = Bb + (size_t)kt * 128;
        #pragma unroll
        for (int i = 0; i < 4; i++) {
            int row = ldrow + i * 32;
            cp16(shi + SW128(row * 128 + ldcol), ahsrc + (size_t)row * rstrideA + ldcol);
            if (TERMS == 2)
                cp16(slo + SW128(row * 128 + ldcol), alsrc + (size_t)row * rstrideA + ldcol);
        }
        #pragma unroll
        for (int i = 0; i < 8; i++) {
            int row = ldrow + i * 32;
            cp16(sbp + SW128(row * 128 + ldcol), bsrc + (size_t)row * rstrideB + ldcol);
        }
    };

    float acc[4][8][4];
    #pragma unroll
    for (int i = 0; i < 4; i++)
        #pragma unroll
        for (int j = 0; j < 8; j++)
            #pragma unroll
            for (int q = 0; q < 4; q++) acc[i][j][q] = 0.f;

    const int aRow  = wm * 64 + (lane & 15);
    const int aKoff = (lane >> 4) << 4;
    const int bRow  = wn * 64 + ((lane >> 4) << 3) + (lane & 7);
    const int bKoff = ((lane >> 3) & 1) << 4;

    load_tile(0, 0); cp_commit();
    load_tile(1, 1); cp_commit();

    for (int kt = 0; kt < KT; kt++) {
        cp_wait<1>();
        __syncthreads();
        int st = kt % N_STG;
        if (kt + 2 < KT) load_tile(kt + 2, (kt + 2) % N_STG);
        cp_commit();

        uint32_t shi = sb0 + st * STAGE_B;
        uint32_t slo = shi + AHI_ST;
        uint32_t sbp = shi + B_OFF;

        #pragma unroll
        for (int j = 0; j < 4; j++) {
            uint32_t ahf[4][4], alf[4][4], bf[4][4];
            #pragma unroll
            for (int im = 0; im < 4; im++) {
                int row = aRow + im * 16;
                uint32_t off = row * 128 + ((j * 32 + aKoff) ^ ((row & 7) << 4));
                ldsm4(ahf[im], shi + off);
                if (TERMS == 2) ldsm4(alf[im], slo + off);
            }
            #pragma unroll
            for (int in2 = 0; in2 < 4; in2++) {
                int row = bRow + in2 * 16;
                ldsm4(bf[in2], sbp + row * 128 + ((j * 32 + bKoff) ^ ((row & 7) << 4)));
            }
            #pragma unroll
            for (int im = 0; im < 4; im++)
                #pragma unroll
                for (int inn = 0; inn < 8; inn++) {
                    mma16816(acc[im][inn], ahf[im], &bf[inn >> 1][(inn & 1) * 2]);
                    if (TERMS == 2)
                        mma16816(acc[im][inn], alf[im], &bf[inn >> 1][(inn & 1) * 2]);
                }
        }
    }

    const int crow0 = bm + wm * 64 + (lane >> 2);
    const int ccol0 = bn + wn * 64 + (lane & 3) * 2;
    #pragma unroll
    for (int im = 0; im < 4; im++) {
        #pragma unroll
        for (int inn = 0; inn < 8; inn++) {
            int col = ccol0 + inn * 8;
            if (col + 1 < Nreal) {
                int r0 = crow0 + im * 16;
                *(float2*)&C[(size_t)r0 * ldC + col]       = make_float2(acc[im][inn][0], acc[im][inn][1]);
                *(float2*)&C[(size_t)(r0 + 8) * ldC + col] = make_float2(acc[im][inn][2], acc[im][inn][3]);
            } else if (col < Nreal) {
                int r0 = crow0 + im * 16;
                C[(size_t)r0 * ldC + col]       = acc[im][inn][0];
                C[(size_t)(r0 + 8) * ldC + col] = acc[im][inn][2];
            }
        }
    }
}

// ================= split kernels =================
__device__ __forceinline__ void split2h(float x, __half& hi, __half& lo) {
    hi = __float2half_rn(x);
    lo = __float2half_rn(x - __half2float(hi));
}

__global__ void split_a_kernel(const float* __restrict__ in, __half* __restrict__ out, int K)
{
    int idx = blockIdx.x * 256 + threadIdx.x;
    int m = idx / K, k = idx - m * K;
    float x = in[idx];
    __half hi, lo; split2h(x, hi, lo);
    size_t ro = (size_t)m * 2 * K;
    out[ro + k] = hi; out[ro + K + k] = lo;
}

__global__ void split_b_kernel(const float* __restrict__ in, __half* __restrict__ out,
                               int K, int N, int Npad)
{
    __shared__ float t[32][33];
    int n0 = blockIdx.x * 32, k0 = blockIdx.y * 32;
    int tx = threadIdx.x, ty = threadIdx.y;
    #pragma unroll
    for (int i = 0; i < 4; i++) {
        int k = k0 + ty + i * 8, n = n0 + tx;
        t[ty + i * 8][tx] = (n < N) ? in[(size_t)k * N + n] : 0.f;
    }
    __syncthreads();
    #pragma unroll
    for (int i = 0; i < 4; i++) {
        int n = n0 + ty + i * 8, k = k0 + tx;
        if (n < Npad)
            out[(size_t)n * K + k] = __float2half_rn(t[tx][ty + i * 8]);
    }
}

// ================= conv + silu =================
__global__ void conv_silu_kernel(const float* __restrict__ cw, const float* __restrict__ cb)
{
    int c = blockIdx.x * 128 + threadIdx.x;
    if (c >= CONVDIM) return;
    int b = blockIdx.z, l0 = blockIdx.y * 64;
    float w0 = cw[c*4+0], w1 = cw[c*4+1], w2 = cw[c*4+2], w3 = cw[c*4+3];
    float bias = cb[c];
    const float* src = g_zx  + (size_t)b * SEQL * INDIM + DINNER + c;
    float*       dst = g_xbc + (size_t)b * SEQL * CONVDIM + c;
    float x0 = (l0 - 3 >= 0) ? src[(size_t)(l0-3) * INDIM] : 0.f;
    float x1 = (l0 - 2 >= 0) ? src[(size_t)(l0-2) * INDIM] : 0.f;
    float x2 = (l0 - 1 >= 0) ? src[(size_t)(l0-1) * INDIM] : 0.f;
    for (int l = l0; l < l0 + 64; l++) {
        float x3 = src[(size_t)l * INDIM];
        float v  = bias + w0*x0 + w1*x1 + w2*x2 + w3*x3;
        dst[(size_t)l * CONVDIM] = v / (1.f + __expf(-v));
        x0 = x1; x1 = x2; x2 = x3;
    }
}

// ================= dt: softplus + dA =================
__global__ void dt_kernel(const float* __restrict__ A_log, const float* __restrict__ dt_bias)
{
    int idx = blockIdx.x * blockDim.x + threadIdx.x;
    if (idx >= NROWS * NHEADS) return;
    int row = idx >> 6, h = idx & 63;
    float raw = g_zx[(size_t)row * INDIM + DTCOL + h] + dt_bias[h];
    float dt  = (raw > 20.f) ? raw : log1pf(expf(raw));
    g_dtv[idx] = dt;
    g_dAv[idx] = expf(dt * -expf(A_log[h]));
}

// ================= chunked scan: phase A =================
__global__ void scanA_kernel()
{
    int bh = blockIdx.x;
    int c  = blockIdx.y;
    int b = bh >> 6, h = bh & 63, p = threadIdx.x;

    float st[DSTATE];
    #pragma unroll
    for (int n = 0; n < DSTATE; n++) st[n] = 0.f;
    float pprod = 1.f;

    const size_t xbase = (size_t)b * SEQL * CONVDIM;
    for (int i = 0; i < CHL; i++) {
        int l = c * CHL + i;
        const float* r = g_xbc + xbase + (size_t)l * CONVDIM;
        int rowi = b * SEQL + l;
        float x = r[h * HEADDIM + p];
        const float4* Bp = (const float4*)(r + DINNER);
        float4 b0 = Bp[0], b1 = Bp[1], b2 = Bp[2], b3 = Bp[3];
        float bb[16] = { b0.x,b0.y,b0.z,b0.w, b1.x,b1.y,b1.z,b1.w,
                         b2.x,b2.y,b2.z,b2.w, b3.x,b3.y,b3.z,b3.w };
        float dt = g_dtv[rowi * NHEADS + h];
        float dA = g_dAv[rowi * NHEADS + h];
        float dtx = dt * x;
        #pragma unroll
        for (int n = 0; n < DSTATE; n++) st[n] = st[n] * dA + dtx * bb[n];
        pprod *= dA;
    }
    float* Sout = g_S + ((size_t)c * NBH + bh) * (HEADDIM * DSTATE) + p * DSTATE;
    #pragma unroll
    for (int n = 0; n < DSTATE; n++) Sout[n] = st[n];
    if (p == 0) g_P[c * NBH + bh] = pprod;
}

// ================= phase B =================
__global__ void scanB_kernel()
{
    int bh = blockIdx.x;
    int p  = threadIdx.x;
    float h[DSTATE];
    #pragma unroll
    for (int n = 0; n < DSTATE; n++) h[n] = 0.f;

    for (int c = 0; c < NCHUNK; c++) {
        size_t base = ((size_t)c * NBH + bh) * (HEADDIM * DSTATE) + p * DSTATE;
        float* Hout = g_Hinit + base;
        #pragma unroll
        for (int n = 0; n < DSTATE; n++) Hout[n] = h[n];
        float P = g_P[c * NBH + bh];
        const float* Sin = g_S + base;
        #pragma unroll
        for (int n = 0; n < DSTATE; n++) h[n] = h[n] * P + Sin[n];
    }
}

// ================= phase C =================
__global__ void scanC_kernel(const float* __restrict__ D_skip)
{
    int bh = blockIdx.x;
    int c  = blockIdx.y;
    int b = bh >> 6, h = bh & 63, p = threadIdx.x;

    float st[DSTATE];
    const float* Hin = g_Hinit + ((size_t)c * NBH + bh) * (HEADDIM * DSTATE) + p * DSTATE;
    #pragma unroll
    for (int n = 0; n < DSTATE; n++) st[n] = Hin[n];

    const float Dh = D_skip[h];
    const size_t xbase = (size_t)b * SEQL * CONVDIM;
    for (int i = 0; i < CHL; i++) {
        int l = c * CHL + i;
        const float* r = g_xbc + xbase + (size_t)l * CONVDIM;
        int rowi = b * SEQL + l;
        float x = r[h * HEADDIM + p];
        const float4* Bp = (const float4*)(r + DINNER);
        const float4* Cp = (const float4*)(r + DINNER + DSTATE);
        float4 b0 = Bp[0], b1 = Bp[1], b2 = Bp[2], b3 = Bp[3];
        float4 c0 = Cp[0], c1 = Cp[1], c2 = Cp[2], c3 = Cp[3];
        float bb[16] = { b0.x,b0.y,b0.z,b0.w, b1.x,b1.y,b1.z,b1.w,
                         b2.x,b2.y,b2.z,b2.w, b3.x,b3.y,b3.z,b3.w };
        float cc[16] = { c0.x,c0.y,c0.z,c0.w, c1.x,c1.y,c1.z,c1.w,
                         c2.x,c2.y,c2.z,c2.w, c3.x,c3.y,c3.z,c3.w };
        float dt = g_dtv[rowi * NHEADS + h];
        float dA = g_dAv[rowi * NHEADS + h];
        float dtx = dt * x;
        float y0 = 0.f, y1 = 0.f, y2 = 0.f, y3 = 0.f;
        #pragma unroll
        for (int n = 0; n < DSTATE; n += 4) {
            st[n+0] = st[n+0] * dA + dtx * bb[n+0]; y0 += st[n+0] * cc[n+0];
            st[n+1] = st[n+1] * dA + dtx * bb[n+1]; y1 += st[n+1] * cc[n+1];
            st[n+2] = st[n+2] * dA + dtx * bb[n+2]; y2 += st[n+2] * cc[n+2];
            st[n+3] = st[n+3] * dA + dtx * bb[n+3]; y3 += st[n+3] * cc[n+3];
        }
        float y = (y0 + y1) + (y2 + y3);
        float g = g_zx[(size_t)rowi * INDIM + h * HEADDIM + p];
        float sg = g / (1.f + __expf(-g));
        g_y[(size_t)rowi * DINNER + h * HEADDIM + p] = (y + Dh * x) * sg;
    }
}

// ================= RMSNorm fused with hi-only A-hat for GEMM2 =================
__global__ void rmsnorm_split_kernel(const float* __restrict__ norm_w, __half* __restrict__ out)
{
    int row = blockIdx.x, tid = threadIdx.x;
    const float* r = g_y + (size_t)row * DINNER;
    float ss = 0.f;
    for (int c = tid; c < DINNER; c += 256) { float v = r[c]; ss += v * v; }
    __shared__ float red[256];
    red[tid] = ss;
    __syncthreads();
    #pragma unroll
    for (int s = 128; s > 0; s >>= 1) { if (tid < s) red[tid] += red[tid + s]; __syncthreads(); }
    float rstd = rsqrtf(red[0] / (float)DINNER + 1e-5f);
    size_t ro = (size_t)row * DINNER;
    for (int c = tid; c < DINNER; c += 256)
        out[ro + c] = __float2half_rn(r[c] * rstd * norm_w[c]);
}

// ================= launch =================
extern "C" void kernel_launch(void* const* d_in, const int* in_sizes, int n_in,
                              void* d_out, int out_size)
{
    const float* hs      = (const float*)d_in[0];
    const float* W_in    = (const float*)d_in[1];
    const float* conv_w  = (const float*)d_in[2];
    const float* conv_b  = (const float*)d_in[3];
    const float* A_log   = (const float*)d_in[4];
    const float* D_skip  = (const float*)d_in[5];
    const float* dt_bias = (const float*)d_in[6];
    const float* norm_w  = (const float*)d_in[7];
    const float* W_out   = (const float*)d_in[8];
    float* out = (float*)d_out;

    float *zx = nullptr;
    __half *ah1, *bh1, *ah2, *bh2;
    cudaGetSymbolAddress((void**)&zx,  g_zx);
    cudaGetSymbolAddress((void**)&ah1, g_ah1);
    cudaGetSymbolAddress((void**)&bh1, g_bh1);
    cudaGetSymbolAddress((void**)&ah2, g_ah2);
    cudaGetSymbolAddress((void**)&bh2, g_bh2);

    cudaFuncSetAttribute(gemm_mma<2,2>, cudaFuncAttributeMaxDynamicSharedMemorySize, GEMM_SMEM);
    cudaFuncSetAttribute(gemm_mma<1,2>, cudaFuncAttributeMaxDynamicSharedMemorySize, GEMM_SMEM);
    cudaFuncSetAttribute(gemm_mma<1,1>, cudaFuncAttributeMaxDynamicSharedMemorySize, GEMM_SMEM);

    split_a_kernel<<<(NROWS * DMODEL) / 256, 256>>>(hs, ah1, DMODEL);
    split_b_kernel<<<dim3(NPAD1 / 32, DMODEL / 32), dim3(32, 8)>>>(W_in, bh1, DMODEL, INDIM, NPAD1);
    split_b_kernel<<<dim3(NPAD2 / 32, DINNER / 32), dim3(32, 8)>>>(W_out, bh2, DINNER, DMODEL, NPAD2);

    // 1a) cols [0, 8192): gate + x — hi-only (linear paths; fp16 rounding adds ~2e-4 in quadrature)
    gemm_mma<1,2><<<dim3(N1TERM / 256, NROWS / 128), 256, GEMM_SMEM>>>(ah1, bh1, zx, DMODEL, N1TERM, INDIM);

    // 1b) cols [8192, 8448): B, C, dt — 2-term (scan-sensitive; dt error amplifies via exp(dt*A))
    gemm_mma<2,2><<<dim3(1, NROWS / 128), 256, GEMM_SMEM>>>(
        ah1, bh1 + (size_t)N1TERM * DMODEL, zx + N1TERM, DMODEL, INDIM - N1TERM, INDIM);

    // 2) conv + dt
    conv_silu_kernel<<<dim3((CONVDIM + 127) / 128, SEQL / 64, BATCH), 128>>>(conv_w, conv_b);
    dt_kernel<<<(NROWS * NHEADS) / 256, 256>>>(A_log, dt_bias);

    // 3) chunked parallel scan
    scanA_kernel<<<dim3(NBH, NCHUNK), HEADDIM>>>();
    scanB_kernel<<<NBH, HEADDIM>>>();
    scanC_kernel<<<dim3(NBH, NCHUNK), HEADDIM>>>(D_skip);

    // 4) rmsnorm + hi-only fp16 cast
    rmsnorm_split_kernel<<<NROWS, 256>>>(norm_w, ah2);

    // 5) out = y @ W_out   (single-term fp16)
    gemm_mma<1,1><<<dim3(NPAD2 / 256, NROWS / 128), 256, GEMM_SMEM>>>(ah2, bh2, out, DINNER, DMODEL, DMODEL);
}